// round 15
// baseline (speedup 1.0000x reference)
#include <cuda_runtime.h>
#include <cuda_fp16.h>
#include <cstdint>

#define N_NODES 100000
#define N_EDGES 1600000
#define D       64
#define DH      128
#define KIN     192

#define TILE_E   64
#define N_TILES  (N_EDGES / TILE_E)   // 25000
#define EK_GRID  148
#define EK_THREADS 512                // 2 groups x 256

// ---------------- edge-kernel smem byte offsets ------------------------------
#define OFF_W1E   0          // W1e^T fp16 [128 rows][36 w] = 18432
#define OFF_W2    18432      // W2^T [64 rows][68 w] = 17408
#define OFF_WEE   35840      // We_e^T (K=64) [64 rows][36 w] = 9216
#define OFF_P     45056      // P^T = (W2@We_m)^T [64 rows][68 w] = 17408
#define OFF_BI1H  62464      // b1 half2 = 256
#define OFF_BI2   62720      // b2 fp32 = 256
#define OFF_BIE2  62976      // be' fp32 = 256
#define OFF_GRP   63232
// group block: X 64x100 w 25600 | HSR/mf 64x68 w 17408 | ridx 256 | EOUT 64x68 f 17408
#define GRP_BYTES 60672
#define GOFF_HSR  25600
#define GOFF_RIDX 43008
#define GOFF_EOUT 43264
#define SMEM_EDGE_BYTES (OFF_GRP + 2 * GRP_BYTES)   // 184576

#define XSTRW 100            // X row stride in words
#define HSTRW 68             // HSR/mf/EOUT row stride in words

// ---------------- precompute-kernel smem -------------------------------------
#define POFF_WS   0
#define POFF_WR   18432
#define POFF_PL   36864
#define SMEM_PRE_BYTES 45056

// ---------------- helpers ----------------------------------------------------
__device__ __forceinline__ uint32_t packh2(float lo, float hi) {
    uint32_t d;
    asm("cvt.rn.f16x2.f32 %0, %1, %2;" : "=r"(d) : "f"(hi), "f"(lo));
    return d;
}
__device__ __forceinline__ void mma16(float* c, const uint32_t* a, const uint32_t* b) {
    asm volatile(
        "mma.sync.aligned.m16n8k16.row.col.f32.f16.f16.f32 "
        "{%0,%1,%2,%3}, {%4,%5,%6,%7}, {%8,%9}, {%0,%1,%2,%3};"
        : "+f"(c[0]), "+f"(c[1]), "+f"(c[2]), "+f"(c[3])
        : "r"(a[0]), "r"(a[1]), "r"(a[2]), "r"(a[3]), "r"(b[0]), "r"(b[1]));
}
__device__ __forceinline__ void ldsm4(uint32_t* r, uint32_t saddr) {
    asm volatile("ldmatrix.sync.aligned.m8n8.x4.shared.b16 {%0,%1,%2,%3}, [%4];"
        : "=r"(r[0]), "=r"(r[1]), "=r"(r[2]), "=r"(r[3]) : "r"(saddr));
}
__device__ __forceinline__ void red4(float* p, float4 v) {
    asm volatile("red.global.add.v4.f32 [%0], {%1,%2,%3,%4};"
        :: "l"(p), "f"(v.x), "f"(v.y), "f"(v.z), "f"(v.w) : "memory");
}

// ---------------- scratch ----------------------------------------------------
__device__ float  g_agg[(size_t)N_NODES * D];
__device__ __half g_H1[(size_t)N_NODES * DH];
__device__ __half g_H2[(size_t)N_NODES * DH];
__device__ __half g_P[DH * D];      // W2 @ We_m  (fp16)
__device__ float  g_be2[D];         // b2 @ We_m + be

__global__ void zero_agg_kernel() {
    size_t i = (size_t)blockIdx.x * blockDim.x + threadIdx.x;
    size_t n4 = (size_t)N_NODES * D / 4;
    if (i < n4) ((float4*)g_agg)[i] = make_float4(0.f, 0.f, 0.f, 0.f);
}

// ---------------- tiny: P = W2 @ We_m,  be' = b2 @ We_m + be -----------------
__global__ void __launch_bounds__(256)
pw_kernel(const float* __restrict__ W2, const float* __restrict__ We,
          const float* __restrict__ b2, const float* __restrict__ be)
{
    int i = blockIdx.x * 256 + threadIdx.x;
    if (i < DH * D) {
        int k = i / D, c = i % D;
        float s = 0.f;
        #pragma unroll 8
        for (int l = 0; l < D; l++)
            s += W2[k * D + l] * We[(D + l) * D + c];
        g_P[k * D + c] = __float2half_rn(s);
    }
    if (i < D) {
        float s = be[i];
        #pragma unroll 8
        for (int l = 0; l < D; l++)
            s += b2[l] * We[(D + l) * D + i];
        g_be2[i] = s;
    }
}

// ---------------- precompute: H1 = h@W1s, H2 = h@W1r -------------------------
__global__ void __launch_bounds__(256)
pre_kernel(const float* __restrict__ h, const float* __restrict__ W1)
{
    extern __shared__ char smc[];
    uint32_t* WSw = (uint32_t*)(smc + POFF_WS);
    uint32_t* WRw = (uint32_t*)(smc + POFF_WR);
    uint32_t* PW  = (uint32_t*)(smc + POFF_PL);

    const int tid  = threadIdx.x;
    const int w    = tid >> 5;
    const int lane = tid & 31;
    const int g    = lane >> 2;
    const int tig  = lane & 3;
    const int swz  = tig << 3;

    for (int i = tid; i < DH * 32; i += 256) {
        int c = i >> 5, k2 = i & 31;
        WSw[c * 36 + k2] = packh2(W1[(64 + 2 * k2) * DH + c],
                                  W1[(64 + 2 * k2 + 1) * DH + c]);
        WRw[c * 36 + k2] = packh2(W1[(128 + 2 * k2) * DH + c],
                                  W1[(128 + 2 * k2 + 1) * DH + c]);
    }
    __syncthreads();

    const int base = blockIdx.x * 64;
    {
        const int nl = tid & 63;
        const int p4 = tid >> 6;
        const int node = base + nl;
        #pragma unroll
        for (int q = 0; q < 4; q++) {
            float4 v = (node < N_NODES)
                ? ((const float4*)(h + (size_t)node * D))[p4 * 4 + q]
                : make_float4(0.f, 0.f, 0.f, 0.f);
            int p = p4 * 8 + q * 2;
            PW[p * 64 + (nl ^ ((p & 3) << 3))]             = packh2(v.x, v.y);
            PW[(p + 1) * 64 + (nl ^ (((p + 1) & 3) << 3))] = packh2(v.z, v.w);
        }
    }
    __syncthreads();

    const int c0 = (w & 3) * 32;
    const int n0 = (w >> 2) * 32;

    float accS[2][4][4], accR[2][4][4];
    #pragma unroll
    for (int mt = 0; mt < 2; mt++)
        #pragma unroll
        for (int nt = 0; nt < 4; nt++)
            #pragma unroll
            for (int q = 0; q < 4; q++) { accS[mt][nt][q] = 0.f; accR[mt][nt][q] = 0.f; }

    #pragma unroll
    for (int kt = 0; kt < 4; kt++) {
        const int k8 = kt * 8;
        uint32_t as[2][4], ar[2][4];
        #pragma unroll
        for (int mt = 0; mt < 2; mt++) {
            int r = c0 + 16 * mt + g;
            as[mt][0] = WSw[r * 36 + k8 + tig];
            as[mt][1] = WSw[(r + 8) * 36 + k8 + tig];
            as[mt][2] = WSw[r * 36 + k8 + tig + 4];
            as[mt][3] = WSw[(r + 8) * 36 + k8 + tig + 4];
            ar[mt][0] = WRw[r * 36 + k8 + tig];
            ar[mt][1] = WRw[(r + 8) * 36 + k8 + tig];
            ar[mt][2] = WRw[r * 36 + k8 + tig + 4];
            ar[mt][3] = WRw[(r + 8) * 36 + k8 + tig + 4];
        }
        uint32_t bv[4][2];
        const int p0 = k8 + tig;
        #pragma unroll
        for (int nt = 0; nt < 4; nt++) {
            int es = (n0 + nt * 8 + g) ^ swz;
            bv[nt][0] = PW[p0 * 64 + es];
            bv[nt][1] = PW[(p0 + 4) * 64 + es];
        }
        #pragma unroll
        for (int mt = 0; mt < 2; mt++)
            #pragma unroll
            for (int nt = 0; nt < 4; nt++) {
                mma16(accS[mt][nt], as[mt], bv[nt]);
                mma16(accR[mt][nt], ar[mt], bv[nt]);
            }
    }

    #pragma unroll
    for (int mt = 0; mt < 2; mt++)
        #pragma unroll
        for (int nt = 0; nt < 4; nt++) {
            int cA = c0 + 16 * mt + g;
            int nA = n0 + 8 * nt + 2 * tig;
            int d0 = base + nA, d1 = base + nA + 1;
            if (d0 < N_NODES) {
                g_H1[(size_t)d0 * DH + cA]     = __float2half_rn(accS[mt][nt][0]);
                g_H1[(size_t)d0 * DH + cA + 8] = __float2half_rn(accS[mt][nt][2]);
                g_H2[(size_t)d0 * DH + cA]     = __float2half_rn(accR[mt][nt][0]);
                g_H2[(size_t)d0 * DH + cA + 8] = __float2half_rn(accR[mt][nt][2]);
            }
            if (d1 < N_NODES) {
                g_H1[(size_t)d1 * DH + cA]     = __float2half_rn(accS[mt][nt][1]);
                g_H1[(size_t)d1 * DH + cA + 8] = __float2half_rn(accS[mt][nt][3]);
                g_H2[(size_t)d1 * DH + cA]     = __float2half_rn(accR[mt][nt][1]);
                g_H2[(size_t)d1 * DH + cA + 8] = __float2half_rn(accR[mt][nt][3]);
            }
        }
}

// ---------------- fused edge kernel ------------------------------------------
__global__ void __launch_bounds__(EK_THREADS, 1)
edge_kernel(const float* __restrict__ h, const float* __restrict__ e,
            const int* __restrict__ senders, const int* __restrict__ receivers,
            const float* __restrict__ W1, const float* __restrict__ b1,
            const float* __restrict__ W2, const float* __restrict__ b2,
            const float* __restrict__ We, const float* __restrict__ be,
            float* __restrict__ out_e)
{
    extern __shared__ char smc[];
    uint32_t* W1w  = (uint32_t*)(smc + OFF_W1E);
    uint32_t* W2w  = (uint32_t*)(smc + OFF_W2);
    uint32_t* WEew = (uint32_t*)(smc + OFF_WEE);
    uint32_t* Pw   = (uint32_t*)(smc + OFF_P);
    uint32_t* b1h  = (uint32_t*)(smc + OFF_BI1H);
    float* bi2  = (float*)(smc + OFF_BI2);
    float* bie2 = (float*)(smc + OFF_BIE2);

    const int tid = threadIdx.x;

    // ---- stage weights + biases ---------------------------------------------
    for (int i = tid; i < DH * 32; i += EK_THREADS) {         // W1e
        int c = i >> 5, k2 = i & 31;
        W1w[c * 36 + k2] = packh2(W1[(2 * k2) * DH + c], W1[(2 * k2 + 1) * DH + c]);
    }
    for (int i = tid; i < D * (DH / 2); i += EK_THREADS) {    // W2
        int c = i >> 6, k2 = i & 63;
        W2w[c * 68 + k2] = packh2(W2[(2 * k2) * D + c], W2[(2 * k2 + 1) * D + c]);
    }
    for (int i = tid; i < D * 32; i += EK_THREADS) {          // We_e (K=64)
        int c = i >> 5, k2 = i & 31;
        WEew[c * 36 + k2] = packh2(We[(2 * k2) * D + c], We[(2 * k2 + 1) * D + c]);
    }
    for (int i = tid; i < D * (DH / 2); i += EK_THREADS) {    // P (fp16 source)
        int c = i >> 6, k2 = i & 63;
        __half2 h2 = __halves2half2(g_P[(2 * k2) * D + c], g_P[(2 * k2 + 1) * D + c]);
        Pw[c * 68 + k2] = *(uint32_t*)&h2;
    }
    if (tid < D) b1h[tid]  = packh2(b1[2 * tid], b1[2 * tid + 1]);
    if (tid < D) bi2[tid]  = b2[tid];
    if (tid < D) bie2[tid] = g_be2[tid];
    __syncthreads();

    // ---- group-local state ---------------------------------------------------
    const int gi   = tid >> 8;
    const int lt   = tid & 255;
    const int w    = lt >> 5;
    const int lane = lt & 31;
    const int g    = lane >> 2;
    const int tig  = lane & 3;

    char* gbase = smc + OFF_GRP + gi * GRP_BYTES;
    uint32_t* Xw   = (uint32_t*)gbase;
    __half*   Xh   = (__half*)gbase;
    uint32_t* HSRw = (uint32_t*)(gbase + GOFF_HSR);
    float*    mf   = (float*)(gbase + GOFF_HSR);   // overlays HSR (time-disjoint)
    int*      ridx = (int*)(gbase + GOFF_RIDX);
    float*    eout = (float*)(gbase + GOFF_EOUT);

    const uint32_t Xs   = (uint32_t)__cvta_generic_to_shared(Xw);
    const uint32_t W1s  = (uint32_t)__cvta_generic_to_shared(W1w);
    const uint32_t W2s  = (uint32_t)__cvta_generic_to_shared(W2w);
    const uint32_t WEes = (uint32_t)__cvta_generic_to_shared(WEew);
    const uint32_t Ps   = (uint32_t)__cvta_generic_to_shared(Pw);

    const int c0w1 = (w & 3) * 32;
    const int e0w1 = (w >> 2) * 32;
    const int wl   = w & 3;
    const int c0w2 = (wl & 1) * 32;
    const int e0w2 = (wl >> 1) * 32;
    const int barid  = gi + 1;       // group-wide (256)
    const int barid2 = gi + 3;       // w0-3 half-group (128)
    const int barid3 = gi + 5;       // w4-7 half-group (128)

    // ldmatrix lane-address components
    const int rA  = (lane & 7) + ((lane >> 3) & 1) * 8;
    const int cA4 = (lane >> 4) << 2;
    const int rB  = (lane & 7) + ((lane >> 4) << 3);
    const int cB4 = ((lane >> 3) & 1) << 2;

    const uint32_t aW1b  = W1s  + ((c0w1 + rA) * 36 + cA4) * 4;
    const uint32_t aW2b  = W2s  + ((c0w2 + rA) * 68 + cA4) * 4;
    const uint32_t aWEeb = WEes + ((c0w2 + rA) * 36 + cA4) * 4;
    const uint32_t aPb   = Ps   + ((c0w2 + rA) * 68 + cA4) * 4;
    const uint32_t bX1b  = Xs + ((e0w1 + rB) * XSTRW + cB4) * 4;
    const uint32_t bX2b  = Xs + ((e0w2 + rB) * XSTRW + cB4) * 4;

    // gather lane maps
    const int el2 = lt >> 2;         // H gather: edge (4 lanes per edge)
    const int p4r = lt & 3;          // H gather: quarter

    #define BARG() asm volatile("bar.sync %0, 256;" :: "r"(barid) : "memory")

    for (int tile = blockIdx.x * 2 + gi; tile < N_TILES; tile += 2 * gridDim.x) {
        const int base = tile * TILE_E;
        BARG();   // S0: prev scatter + e_new copy done; all group smem reusable

        // ====== gather (coalesced): e -> X rows; H1[s]+H2[r]+b1 -> HSR =======
        {
            // --- e: fully coalesced linear loads, scatter-store to X rows ----
            const float4* e4 = (const float4*)(e + (size_t)base * D);
            #pragma unroll
            for (int q = 0; q < 4; q++) {
                int gidx = lt + q * 256;             // 0..1023 float4s
                float4 v = e4[gidx];
                int ed = gidx >> 4, ch = gidx & 15;
                *(uint2*)(Xw + ed * XSTRW + ch * 2) =
                    make_uint2(packh2(v.x, v.y), packh2(v.z, v.w));
            }

            // --- H: 4 lanes per edge row (sector-efficient) ------------------
            const int sI = senders[base + el2];
            const int rI = receivers[base + el2];
            if (p4r == 0) ridx[el2] = rI;

            const uint4* h1p = (const uint4*)(g_H1 + (size_t)sI * DH) + p4r * 4;
            const uint4* h2p = (const uint4*)(g_H2 + (size_t)rI * DH) + p4r * 4;
            uint32_t hw[16];
            #pragma unroll
            for (int q = 0; q < 4; q++) {
                uint4 a = h1p[q], b = h2p[q];
                const __half2* bb = (const __half2*)(b1h + (p4r * 4 + q) * 4);
                __half2 s0 = __hadd2(__hadd2(*(__half2*)&a.x, *(__half2*)&b.x), bb[0]);
                __half2 s1 = __hadd2(__hadd2(*(__half2*)&a.y, *(__half2*)&b.y), bb[1]);
                __half2 s2 = __hadd2(__hadd2(*(__half2*)&a.z, *(__half2*)&b.z), bb[2]);
                __half2 s3 = __hadd2(__hadd2(*(__half2*)&a.w, *(__half2*)&b.w), bb[3]);
                hw[q * 4 + 0] = *(uint32_t*)&s0;
                hw[q * 4 + 1] = *(uint32_t*)&s1;
                hw[q * 4 + 2] = *(uint32_t*)&s2;
                hw[q * 4 + 3] = *(uint32_t*)&s3;
            }
            uint32_t pw[16];
            #pragma unroll
            for (int bq = 0; bq < 2; bq++) {
                const __half2* s0 = (const __half2*)(hw + bq * 8);
                const __half2* s1 = (const __half2*)(hw + bq * 8 + 4);
                #pragma unroll
                for (int j = 0; j < 4; j++) {
                    __half2 lo = __lows2half2(s0[j], s1[j]);
                    __half2 hi = __highs2half2(s0[j], s1[j]);
                    pw[bq * 8 + 2 * j]     = *(uint32_t*)&lo;
                    pw[bq * 8 + 2 * j + 1] = *(uint32_t*)&hi;
                }
            }
            uint4* hdst = (uint4*)(HSRw + el2 * HSTRW + p4r * 16);
            hdst[0] = make_uint4(pw[0],  pw[1],  pw[2],  pw[3]);
            hdst[1] = make_uint4(pw[4],  pw[5],  pw[6],  pw[7]);
            hdst[2] = make_uint4(pw[8],  pw[9],  pw[10], pw[11]);
            hdst[3] = make_uint4(pw[12], pw[13], pw[14], pw[15]);
        }
        BARG();   // S1

        // ====== GEMM1': acc init = HSR(+b1); += e @ W1e (K=64) ===============
        float acc1[2][4][4];
        {
            const int cpb = 16 * (w & 3);
            #pragma unroll
            for (int mt = 0; mt < 2; mt++)
                #pragma unroll
                for (int nt = 0; nt < 4; nt++) {
                    int eA = e0w1 + 8 * nt + 2 * tig;
                    int cp = cpb + 8 * mt + g;
                    uint32_t v0 = HSRw[eA * HSTRW + cp];
                    uint32_t v1 = HSRw[(eA + 1) * HSTRW + cp];
                    float2 f0 = __half22float2(*(__half2*)&v0);
                    float2 f1 = __half22float2(*(__half2*)&v1);
                    acc1[mt][nt][0] = f0.x; acc1[mt][nt][2] = f0.y;
                    acc1[mt][nt][1] = f1.x; acc1[mt][nt][3] = f1.y;
                }
        }
        #pragma unroll
        for (int kt = 0; kt < 4; kt++) {
            uint32_t av[2][4], bv[2][4];
            ldsm4(av[0], aW1b + kt * 32);
            ldsm4(av[1], aW1b + 2304 + kt * 32);
            ldsm4(bv[0], bX1b + kt * 32);
            ldsm4(bv[1], bX1b + 6400 + kt * 32);
            #pragma unroll
            for (int mt = 0; mt < 2; mt++)
                #pragma unroll
                for (int np = 0; np < 2; np++) {
                    mma16(acc1[mt][2 * np],     av[mt], bv[np]);
                    mma16(acc1[mt][2 * np + 1], av[mt], bv[np] + 2);
                }
        }
        BARG();   // S2

        // ===== epilogue1: hid = relu(acc) -> X halves 64+c ===================
        #pragma unroll
        for (int mt = 0; mt < 2; mt++)
            #pragma unroll
            for (int nt = 0; nt < 4; nt++) {
                int cA = c0w1 + 16 * mt + g;
                int eA = e0w1 + 8 * nt + 2 * tig;
                Xh[eA * 200 + 64 + cA]           = __float2half_rn(fmaxf(acc1[mt][nt][0], 0.f));
                Xh[(eA + 1) * 200 + 64 + cA]     = __float2half_rn(fmaxf(acc1[mt][nt][1], 0.f));
                Xh[eA * 200 + 64 + cA + 8]       = __float2half_rn(fmaxf(acc1[mt][nt][2], 0.f));
                Xh[(eA + 1) * 200 + 64 + cA + 8] = __float2half_rn(fmaxf(acc1[mt][nt][3], 0.f));
            }
        BARG();   // S3

        float acc2[2][4][4];
        #pragma unroll
        for (int mt = 0; mt < 2; mt++)
            #pragma unroll
            for (int nt = 0; nt < 4; nt++)
                #pragma unroll
                for (int q = 0; q < 4; q++) acc2[mt][nt][q] = 0.f;

        if (w < 4) {
            // ===== GEMM2: m = hid @ W2 (K=128) -> mf -> scatter ==============
            #pragma unroll
            for (int kt = 0; kt < 8; kt++) {
                uint32_t av[2][4], bv[2][4];
                ldsm4(av[0], aW2b + kt * 32);
                ldsm4(av[1], aW2b + 4352 + kt * 32);
                ldsm4(bv[0], bX2b + 128 + kt * 32);
                ldsm4(bv[1], bX2b + 6400 + 128 + kt * 32);
                #pragma unroll
                for (int mt = 0; mt < 2; mt++)
                    #pragma unroll
                    for (int np = 0; np < 2; np++) {
                        mma16(acc2[mt][2 * np],     av[mt], bv[np]);
                        mma16(acc2[mt][2 * np + 1], av[mt], bv[np] + 2);
                    }
            }
            #pragma unroll
            for (int mt = 0; mt < 2; mt++)
                #pragma unroll
                for (int nt = 0; nt < 4; nt++) {
                    int cA = c0w2 + 16 * mt + g;
                    int eA = e0w2 + 8 * nt + 2 * tig;
                    mf[eA * HSTRW + cA]           = acc2[mt][nt][0] + bi2[cA];
                    mf[(eA + 1) * HSTRW + cA]     = acc2[mt][nt][1] + bi2[cA];
                    mf[eA * HSTRW + cA + 8]       = acc2[mt][nt][2] + bi2[cA + 8];
                    mf[(eA + 1) * HSTRW + cA + 8] = acc2[mt][nt][3] + bi2[cA + 8];
                }
            asm volatile("bar.sync %0, 128;" :: "r"(barid2) : "memory");
            // scatter: red.global.add.v4.f32
            const int el = lt & 63;
            const int hf = (lt >> 6) & 1;
            const int r  = ridx[el];
            const float4* mrow4 = (const float4*)(mf + el * HSTRW + hf * 32);
            float* dstp = g_agg + (size_t)r * D + hf * 32;
            #pragma unroll
            for (int c4 = 0; c4 < 8; c4++)
                red4(dstp + c4 * 4, mrow4[c4]);
        } else {
            // ===== GEMM3: e @ We_e (K=64) + hid @ P (K=128) ==================
            #pragma unroll
            for (int kt = 0; kt < 4; kt++) {
                uint32_t av[2][4], bv[2][4];
                ldsm4(av[0], aWEeb + kt * 32);
                ldsm4(av[1], aWEeb + 2304 + kt * 32);
                ldsm4(bv[0], bX2b + kt * 32);
                ldsm4(bv[1], bX2b + 6400 + kt * 32);
                #pragma unroll
                for (int mt = 0; mt < 2; mt++)
                    #pragma unroll
                    for (int np = 0; np < 2; np++) {
                        mma16(acc2[mt][2 * np],     av[mt], bv[np]);
                        mma16(acc2[mt][2 * np + 1], av[mt], bv[np] + 2);
                    }
            }
            #pragma unroll
            for (int kt = 0; kt < 8; kt++) {
                uint32_t av[2][4], bv[2][4];
                ldsm4(av[0], aPb + kt * 32);
                ldsm4(av[1], aPb + 4352 + kt * 32);
                ldsm4(bv[0], bX2b + 128 + kt * 32);
                ldsm4(bv[1], bX2b + 6400 + 128 + kt * 32);
                #pragma unroll
                for (int mt = 0; mt < 2; mt++)
                    #pragma unroll
                    for (int np = 0; np < 2; np++) {
                        mma16(acc2[mt][2 * np],     av[mt], bv[np]);
                        mma16(acc2[mt][2 * np + 1], av[mt], bv[np] + 2);
                    }
            }
            // ===== epilogue3: relu(acc + be') -> EOUT (conflict-free STS) ====
            #pragma unroll
            for (int mt = 0; mt < 2; mt++)
                #pragma unroll
                for (int nt = 0; nt < 4; nt++) {
                    int cA = c0w2 + 16 * mt + g;
                    int eA = e0w2 + 8 * nt + 2 * tig;
                    eout[eA * HSTRW + cA]           = fmaxf(acc2[mt][nt][0] + bie2[cA], 0.f);
                    eout[(eA + 1) * HSTRW + cA]     = fmaxf(acc2[mt][nt][1] + bie2[cA], 0.f);
                    eout[eA * HSTRW + cA + 8]       = fmaxf(acc2[mt][nt][2] + bie2[cA + 8], 0.f);
                    eout[(eA + 1) * HSTRW + cA + 8] = fmaxf(acc2[mt][nt][3] + bie2[cA + 8], 0.f);
                }
            asm volatile("bar.sync %0, 128;" :: "r"(barid3) : "memory");
            // ===== coalesced copy EOUT -> out_e (STG.128, linear) ============
            const int lt2 = lt - 128;            // 0..127
            float4* dst4 = (float4*)(out_e + (size_t)base * D);
            #pragma unroll
            for (int jj = 0; jj < 8; jj++) {
                int idx = lt2 + jj * 128;        // 0..1023 float4s
                int row = idx >> 4, ch = idx & 15;
                float4 v = *(const float4*)(eout + row * HSTRW + ch * 4);
                dst4[idx] = v;
            }
        }
    }
    #undef BARG
}

// ---------------- node kernel: h_new = relu([h | agg] @ W_node + b) ----------
#define NT    32
#define NPAD  36
#define NOFF_W 0
#define NOFF_B (NOFF_W + DH * D)
#define NOFF_X (NOFF_B + D)
#define SMEM_NODE_FLOATS (NOFF_X + DH * NPAD)
#define SMEM_NODE_BYTES  (SMEM_NODE_FLOATS * 4)

__global__ void __launch_bounds__(128)
node_kernel(const float* __restrict__ h,
            const float* __restrict__ Wn, const float* __restrict__ bn,
            float* __restrict__ out_h)
{
    extern __shared__ float sm[];
    const int tid = threadIdx.x;

    for (int i = tid; i < DH * D / 4; i += 128)
        ((float4*)(sm + NOFF_W))[i] = ((const float4*)Wn)[i];
    if (tid < D) sm[NOFF_B + tid] = bn[tid];
    __syncthreads();

    const int nl   = tid >> 2;
    const int part = tid & 3;
    const int ng   = tid >> 4;
    const int cgc  = tid & 15;

    const int n_tiles = N_NODES / NT;
    for (int tile = blockIdx.x; tile < n_tiles; tile += gridDim.x) {
        const int base = tile * NT;
        {
            const float4* hp = (const float4*)(h + (size_t)(base + nl) * D) + part * 4;
            const float4* ap = (const float4*)(g_agg + (size_t)(base + nl) * D) + part * 4;
            #pragma unroll
            for (int q = 0; q < 4; q++) {
                float4 v = hp[q];
                int k0 = part * 16 + q * 4;
                sm[NOFF_X + (k0 + 0) * NPAD + nl] = v.x;
                sm[NOFF_X + (k0 + 1) * NPAD + nl] = v.y;
                sm[NOFF_X + (k0 + 2) * NPAD + nl] = v.z;
                sm[NOFF_X + (k0 + 3) * NPAD + nl] = v.w;
            }
            #pragma unroll
            for (int q = 0; q < 4; q++) {
                float4 v = ap[q];
                int k0 = 64 + part * 16 + q * 4;
                sm[NOFF_X + (k0 + 0) * NPAD + nl] = v.x;
                sm[NOFF_X + (k0 + 1) * NPAD + nl] = v.y;
                sm[NOFF_X + (k0 + 2) * NPAD + nl] = v.z;
                sm[NOFF_X + (k0 + 3) * NPAD + nl] = v.w;
            }
        }
        __syncthreads();

        float acc[4][4];
        #pragma unroll
        for (int i = 0; i < 4; i++)
            #pragma unroll
            for (int j = 0; j < 4; j++) acc[i][j] = 0.f;

        const float* Xb = sm + NOFF_X + ng * 4;
        const float* Wb = sm + NOFF_W + cgc * 4;
        #pragma unroll 4
        for (int k = 0; k < DH; k++) {
            float4 a = *(const float4*)(Xb + k * NPAD);
            float4 wv4 = *(const float4*)(Wb + k * D);
            float av[4] = {a.x, a.y, a.z, a.w};
            float wv[4] = {wv4.x, wv4.y, wv4.z, wv4.w};
            #pragma unroll
            for (int i = 0; i < 4; i++)
                #pragma unroll
                for (int j = 0; j < 4; j++)
                    acc[i][j] = fmaf(av[i], wv[j], acc[i][j]);
        }
        float bb[4];
        #pragma unroll
        for (int j = 0; j < 4; j++) bb[j] = sm[NOFF_B + cgc * 4 + j];
        #pragma unroll
        for (int i = 0; i < 4; i++) {
            float4 v;
            v.x = fmaxf(acc[i][0] + bb[0], 0.f);
            v.y = fmaxf(acc[i][1] + bb[1], 0.f);
            v.z = fmaxf(acc[i][2] + bb[2], 0.f);
            v.w = fmaxf(acc[i][3] + bb[3], 0.f);
            *(float4*)(out_h + (size_t)(base + ng * 4 + i) * D + cgc * 4) = v;
        }
        __syncthreads();
    }
}

// ---------------- launch -----------------------------------------------------
extern "C" void kernel_launch(void* const* d_in, const int* in_sizes, int n_in,
                              void* d_out, int out_size)
{
    const float* h        = (const float*)d_in[0];
    const float* e        = (const float*)d_in[1];
    const int*   senders  = (const int*)d_in[2];
    const int*   receivers= (const int*)d_in[3];
    const float* W1       = (const float*)d_in[4];
    const float* b1       = (const float*)d_in[5];
    const float* W2       = (const float*)d_in[6];
    const float* b2       = (const float*)d_in[7];
    const float* Wn       = (const float*)d_in[8];
    const float* bn       = (const float*)d_in[9];
    const float* We       = (const float*)d_in[10];
    const float* be       = (const float*)d_in[11];

    float* out_h = (float*)d_out;
    float* out_e = out_h + (size_t)N_NODES * D;

    cudaFuncSetAttribute(edge_kernel, cudaFuncAttributeMaxDynamicSharedMemorySize,
                         SMEM_EDGE_BYTES);
    cudaFuncSetAttribute(node_kernel, cudaFuncAttributeMaxDynamicSharedMemorySize,
                         SMEM_NODE_BYTES);

    zero_agg_kernel<<<(N_NODES * D / 4 + 255) / 256, 256>>>();
    pw_kernel<<<(DH * D + 255) / 256, 256>>>(W2, We, b2, be);
    pre_kernel<<<(N_NODES + 63) / 64, 256, SMEM_PRE_BYTES>>>(h, W1);
    edge_kernel<<<EK_GRID, EK_THREADS, SMEM_EDGE_BYTES>>>(
        h, e, senders, receivers, W1, b1, W2, b2, We, be, out_e);
    node_kernel<<<1480, 128, SMEM_NODE_BYTES>>>(h, Wn, bn, out_h);
}

// round 16
// speedup vs baseline: 1.0395x; 1.0395x over previous
#include <cuda_runtime.h>
#include <cuda_fp16.h>
#include <cstdint>

#define N_NODES 100000
#define N_EDGES 1600000
#define D       64
#define DH      128
#define KIN     192

#define TILE_E   64
#define N_TILES  (N_EDGES / TILE_E)   // 25000
#define EK_GRID  148
#define EK_THREADS 512                // 2 groups x 256

// ---------------- edge-kernel smem byte offsets ------------------------------
#define OFF_W1E   0          // W1e^T fp16 [128 rows][36 w] = 18432
#define OFF_W2    18432      // W2^T [64 rows][68 w] = 17408 (permuted K)
#define OFF_WEE   35840      // We_e^T (K=64) [64 rows][36 w] = 9216
#define OFF_P     45056      // P^T [64 rows][68 w] = 17408 (permuted K)
#define OFF_BI1H  62464      // b1 half2 = 256
#define OFF_BI2   62720      // b2 fp32 = 256
#define OFF_BIE2  62976      // be' fp32 = 256
#define OFF_GRP   63232
// group block: X 64x100 w 25600 | HSR/mf 64x68 w 17408 | ridx 256 | EOUT 64x68 f 17408
#define GRP_BYTES 60672
#define GOFF_HSR  25600
#define GOFF_RIDX 43008
#define GOFF_EOUT 43264
#define SMEM_EDGE_BYTES (OFF_GRP + 2 * GRP_BYTES)   // 184576

#define XSTRW 100            // X row stride in words
#define HSTRW 68             // HSR/mf/EOUT row stride in words

// ---------------- precompute-kernel smem -------------------------------------
#define POFF_WS   0
#define POFF_WR   18432
#define POFF_PL   36864
#define SMEM_PRE_BYTES 45056

// ---------------- node-kernel smem -------------------------------------------
#define NOFF_WN 0            // Wn fragment [64][68] w = 17408
#define NOFF_BN 17408        // 64 floats = 256
#define NOFF_PL 17664        // planes 64 p x 64 w = 16384
#define SMEM_NODE_BYTES 34048

// ---------------- helpers ----------------------------------------------------
__device__ __forceinline__ uint32_t packh2(float lo, float hi) {
    uint32_t d;
    asm("cvt.rn.f16x2.f32 %0, %1, %2;" : "=r"(d) : "f"(hi), "f"(lo));
    return d;
}
__device__ __forceinline__ void mma16(float* c, const uint32_t* a, const uint32_t* b) {
    asm volatile(
        "mma.sync.aligned.m16n8k16.row.col.f32.f16.f16.f32 "
        "{%0,%1,%2,%3}, {%4,%5,%6,%7}, {%8,%9}, {%0,%1,%2,%3};"
        : "+f"(c[0]), "+f"(c[1]), "+f"(c[2]), "+f"(c[3])
        : "r"(a[0]), "r"(a[1]), "r"(a[2]), "r"(a[3]), "r"(b[0]), "r"(b[1]));
}
__device__ __forceinline__ void ldsm4(uint32_t* r, uint32_t saddr) {
    asm volatile("ldmatrix.sync.aligned.m8n8.x4.shared.b16 {%0,%1,%2,%3}, [%4];"
        : "=r"(r[0]), "=r"(r[1]), "=r"(r[2]), "=r"(r[3]) : "r"(saddr));
}
__device__ __forceinline__ void red4(float* p, float4 v) {
    asm volatile("red.global.add.v4.f32 [%0], {%1,%2,%3,%4};"
        :: "l"(p), "f"(v.x), "f"(v.y), "f"(v.z), "f"(v.w) : "memory");
}

// ---------------- scratch ----------------------------------------------------
__device__ float  g_agg[(size_t)N_NODES * D];
__device__ __half g_H1[(size_t)N_NODES * DH];
__device__ __half g_H2[(size_t)N_NODES * DH];
__device__ __half g_P[DH * D];      // W2 @ We_m  (fp16)
__device__ float  g_be2[D];         // b2 @ We_m + be

__global__ void zero_agg_kernel() {
    size_t i = (size_t)blockIdx.x * blockDim.x + threadIdx.x;
    size_t n4 = (size_t)N_NODES * D / 4;
    if (i < n4) ((float4*)g_agg)[i] = make_float4(0.f, 0.f, 0.f, 0.f);
}

// ---------------- tiny: P = W2 @ We_m,  be' = b2 @ We_m + be -----------------
__global__ void __launch_bounds__(256)
pw_kernel(const float* __restrict__ W2, const float* __restrict__ We,
          const float* __restrict__ b2, const float* __restrict__ be)
{
    int i = blockIdx.x * 256 + threadIdx.x;
    if (i < DH * D) {
        int k = i / D, c = i % D;
        float s = 0.f;
        #pragma unroll 8
        for (int l = 0; l < D; l++)
            s += W2[k * D + l] * We[(D + l) * D + c];
        g_P[k * D + c] = __float2half_rn(s);
    }
    if (i < D) {
        float s = be[i];
        #pragma unroll 8
        for (int l = 0; l < D; l++)
            s += b2[l] * We[(D + l) * D + i];
        g_be2[i] = s;
    }
}

// ---------------- precompute: H1 = h@W1s, H2 = h@W1r -------------------------
__global__ void __launch_bounds__(256)
pre_kernel(const float* __restrict__ h, const float* __restrict__ W1)
{
    extern __shared__ char smc[];
    uint32_t* WSw = (uint32_t*)(smc + POFF_WS);
    uint32_t* WRw = (uint32_t*)(smc + POFF_WR);
    uint32_t* PW  = (uint32_t*)(smc + POFF_PL);

    const int tid  = threadIdx.x;
    const int w    = tid >> 5;
    const int lane = tid & 31;
    const int g    = lane >> 2;
    const int tig  = lane & 3;
    const int swz  = tig << 3;

    for (int i = tid; i < DH * 32; i += 256) {
        int c = i >> 5, k2 = i & 31;
        WSw[c * 36 + k2] = packh2(W1[(64 + 2 * k2) * DH + c],
                                  W1[(64 + 2 * k2 + 1) * DH + c]);
        WRw[c * 36 + k2] = packh2(W1[(128 + 2 * k2) * DH + c],
                                  W1[(128 + 2 * k2 + 1) * DH + c]);
    }
    __syncthreads();

    const int base = blockIdx.x * 64;
    {
        const int nl = tid & 63;
        const int p4 = tid >> 6;
        const int node = base + nl;
        #pragma unroll
        for (int q = 0; q < 4; q++) {
            float4 v = (node < N_NODES)
                ? ((const float4*)(h + (size_t)node * D))[p4 * 4 + q]
                : make_float4(0.f, 0.f, 0.f, 0.f);
            int p = p4 * 8 + q * 2;
            PW[p * 64 + (nl ^ ((p & 3) << 3))]             = packh2(v.x, v.y);
            PW[(p + 1) * 64 + (nl ^ (((p + 1) & 3) << 3))] = packh2(v.z, v.w);
        }
    }
    __syncthreads();

    const int c0 = (w & 3) * 32;
    const int n0 = (w >> 2) * 32;

    float accS[2][4][4], accR[2][4][4];
    #pragma unroll
    for (int mt = 0; mt < 2; mt++)
        #pragma unroll
        for (int nt = 0; nt < 4; nt++)
            #pragma unroll
            for (int q = 0; q < 4; q++) { accS[mt][nt][q] = 0.f; accR[mt][nt][q] = 0.f; }

    #pragma unroll
    for (int kt = 0; kt < 4; kt++) {
        const int k8 = kt * 8;
        uint32_t as[2][4], ar[2][4];
        #pragma unroll
        for (int mt = 0; mt < 2; mt++) {
            int r = c0 + 16 * mt + g;
            as[mt][0] = WSw[r * 36 + k8 + tig];
            as[mt][1] = WSw[(r + 8) * 36 + k8 + tig];
            as[mt][2] = WSw[r * 36 + k8 + tig + 4];
            as[mt][3] = WSw[(r + 8) * 36 + k8 + tig + 4];
            ar[mt][0] = WRw[r * 36 + k8 + tig];
            ar[mt][1] = WRw[(r + 8) * 36 + k8 + tig];
            ar[mt][2] = WRw[r * 36 + k8 + tig + 4];
            ar[mt][3] = WRw[(r + 8) * 36 + k8 + tig + 4];
        }
        uint32_t bv[4][2];
        const int p0 = k8 + tig;
        #pragma unroll
        for (int nt = 0; nt < 4; nt++) {
            int es = (n0 + nt * 8 + g) ^ swz;
            bv[nt][0] = PW[p0 * 64 + es];
            bv[nt][1] = PW[(p0 + 4) * 64 + es];
        }
        #pragma unroll
        for (int mt = 0; mt < 2; mt++)
            #pragma unroll
            for (int nt = 0; nt < 4; nt++) {
                mma16(accS[mt][nt], as[mt], bv[nt]);
                mma16(accR[mt][nt], ar[mt], bv[nt]);
            }
    }

    #pragma unroll
    for (int mt = 0; mt < 2; mt++)
        #pragma unroll
        for (int nt = 0; nt < 4; nt++) {
            int cA = c0 + 16 * mt + g;
            int nA = n0 + 8 * nt + 2 * tig;
            int d0 = base + nA, d1 = base + nA + 1;
            if (d0 < N_NODES) {
                g_H1[(size_t)d0 * DH + cA]     = __float2half_rn(accS[mt][nt][0]);
                g_H1[(size_t)d0 * DH + cA + 8] = __float2half_rn(accS[mt][nt][2]);
                g_H2[(size_t)d0 * DH + cA]     = __float2half_rn(accR[mt][nt][0]);
                g_H2[(size_t)d0 * DH + cA + 8] = __float2half_rn(accR[mt][nt][2]);
            }
            if (d1 < N_NODES) {
                g_H1[(size_t)d1 * DH + cA]     = __float2half_rn(accS[mt][nt][1]);
                g_H1[(size_t)d1 * DH + cA + 8] = __float2half_rn(accS[mt][nt][3]);
                g_H2[(size_t)d1 * DH + cA]     = __float2half_rn(accR[mt][nt][1]);
                g_H2[(size_t)d1 * DH + cA + 8] = __float2half_rn(accR[mt][nt][3]);
            }
        }
}

// ---------------- fused edge kernel ------------------------------------------
// hid K-permutation: K-slot word w ∈ [0,64) holds channels
//   lo = 32*(w>>4) + 16*(w&1) + ((w>>1)&7),  hi = lo + 8
// Both X(hid)/HSR storage and W2/P staging use this ordering.
__global__ void __launch_bounds__(EK_THREADS, 1)
edge_kernel(const float* __restrict__ h, const float* __restrict__ e,
            const int* __restrict__ senders, const int* __restrict__ receivers,
            const float* __restrict__ W1, const float* __restrict__ b1,
            const float* __restrict__ W2, const float* __restrict__ b2,
            const float* __restrict__ We, const float* __restrict__ be,
            float* __restrict__ out_e)
{
    extern __shared__ char smc[];
    uint32_t* W1w  = (uint32_t*)(smc + OFF_W1E);
    uint32_t* W2w  = (uint32_t*)(smc + OFF_W2);
    uint32_t* WEew = (uint32_t*)(smc + OFF_WEE);
    uint32_t* Pw   = (uint32_t*)(smc + OFF_P);
    uint32_t* b1h  = (uint32_t*)(smc + OFF_BI1H);
    float* bi2  = (float*)(smc + OFF_BI2);
    float* bie2 = (float*)(smc + OFF_BIE2);

    const int tid = threadIdx.x;

    // ---- stage weights + biases ---------------------------------------------
    for (int i = tid; i < DH * 32; i += EK_THREADS) {         // W1e (natural K)
        int c = i >> 5, k2 = i & 31;
        W1w[c * 36 + k2] = packh2(W1[(2 * k2) * DH + c], W1[(2 * k2 + 1) * DH + c]);
    }
    for (int i = tid; i < D * (DH / 2); i += EK_THREADS) {    // W2 (permuted K)
        int c = i >> 6, kp = i & 63;
        int lo = 32 * (kp >> 4) + 16 * (kp & 1) + ((kp >> 1) & 7);
        W2w[c * 68 + kp] = packh2(W2[lo * D + c], W2[(lo + 8) * D + c]);
    }
    for (int i = tid; i < D * 32; i += EK_THREADS) {          // We_e (natural K)
        int c = i >> 5, k2 = i & 31;
        WEew[c * 36 + k2] = packh2(We[(2 * k2) * D + c], We[(2 * k2 + 1) * D + c]);
    }
    for (int i = tid; i < D * (DH / 2); i += EK_THREADS) {    // P (permuted K)
        int c = i >> 6, kp = i & 63;
        int lo = 32 * (kp >> 4) + 16 * (kp & 1) + ((kp >> 1) & 7);
        __half2 h2 = __halves2half2(g_P[lo * D + c], g_P[(lo + 8) * D + c]);
        Pw[c * 68 + kp] = *(uint32_t*)&h2;
    }
    if (tid < D) b1h[tid]  = packh2(b1[2 * tid], b1[2 * tid + 1]);
    if (tid < D) bi2[tid]  = b2[tid];
    if (tid < D) bie2[tid] = g_be2[tid];
    __syncthreads();

    // ---- group-local state ---------------------------------------------------
    const int gi   = tid >> 8;
    const int lt   = tid & 255;
    const int w    = lt >> 5;
    const int lane = lt & 31;
    const int g    = lane >> 2;
    const int tig  = lane & 3;

    char* gbase = smc + OFF_GRP + gi * GRP_BYTES;
    uint32_t* Xw   = (uint32_t*)gbase;
    uint32_t* HSRw = (uint32_t*)(gbase + GOFF_HSR);
    float*    mf   = (float*)(gbase + GOFF_HSR);   // overlays HSR (time-disjoint)
    int*      ridx = (int*)(gbase + GOFF_RIDX);
    float*    eout = (float*)(gbase + GOFF_EOUT);

    const uint32_t Xs   = (uint32_t)__cvta_generic_to_shared(Xw);
    const uint32_t W1s  = (uint32_t)__cvta_generic_to_shared(W1w);
    const uint32_t W2s  = (uint32_t)__cvta_generic_to_shared(W2w);
    const uint32_t WEes = (uint32_t)__cvta_generic_to_shared(WEew);
    const uint32_t Ps   = (uint32_t)__cvta_generic_to_shared(Pw);

    const int c0w1 = (w & 3) * 32;
    const int e0w1 = (w >> 2) * 32;
    const int wl   = w & 3;
    const int c0w2 = (wl & 1) * 32;
    const int e0w2 = (wl >> 1) * 32;
    const int barid  = gi + 1;       // group-wide (256)
    const int barid2 = gi + 3;       // w0-3 half-group (128)
    const int barid3 = gi + 5;       // w4-7 half-group (128)

    // ldmatrix lane-address components
    const int rA  = (lane & 7) + ((lane >> 3) & 1) * 8;
    const int cA4 = (lane >> 4) << 2;
    const int rB  = (lane & 7) + ((lane >> 4) << 3);
    const int cB4 = ((lane >> 3) & 1) << 2;

    const uint32_t aW1b  = W1s  + ((c0w1 + rA) * 36 + cA4) * 4;
    const uint32_t aW2b  = W2s  + ((c0w2 + rA) * 68 + cA4) * 4;
    const uint32_t aWEeb = WEes + ((c0w2 + rA) * 36 + cA4) * 4;
    const uint32_t aPb   = Ps   + ((c0w2 + rA) * 68 + cA4) * 4;
    const uint32_t bX1b  = Xs + ((e0w1 + rB) * XSTRW + cB4) * 4;
    const uint32_t bX2b  = Xs + ((e0w2 + rB) * XSTRW + cB4) * 4;

    // gather lane maps
    const int el2 = lt >> 2;         // H gather: edge (4 lanes per edge)
    const int p4r = lt & 3;          // H gather: quarter

    #define BARG() asm volatile("bar.sync %0, 256;" :: "r"(barid) : "memory")

    for (int tile = blockIdx.x * 2 + gi; tile < N_TILES; tile += 2 * gridDim.x) {
        const int base = tile * TILE_E;
        BARG();   // S0

        // ====== gather (coalesced): e -> X rows; H1[s]+H2[r]+b1 -> HSR =======
        {
            const float4* e4 = (const float4*)(e + (size_t)base * D);
            #pragma unroll
            for (int q = 0; q < 4; q++) {
                int gidx = lt + q * 256;
                float4 v = e4[gidx];
                int ed = gidx >> 4, ch = gidx & 15;
                *(uint2*)(Xw + ed * XSTRW + ch * 2) =
                    make_uint2(packh2(v.x, v.y), packh2(v.z, v.w));
            }

            const int sI = senders[base + el2];
            const int rI = receivers[base + el2];
            if (p4r == 0) ridx[el2] = rI;

            const uint4* h1p = (const uint4*)(g_H1 + (size_t)sI * DH) + p4r * 4;
            const uint4* h2p = (const uint4*)(g_H2 + (size_t)rI * DH) + p4r * 4;
            uint32_t hw[16];
            #pragma unroll
            for (int q = 0; q < 4; q++) {
                uint4 a = h1p[q], b = h2p[q];
                const __half2* bb = (const __half2*)(b1h + (p4r * 4 + q) * 4);
                __half2 s0 = __hadd2(__hadd2(*(__half2*)&a.x, *(__half2*)&b.x), bb[0]);
                __half2 s1 = __hadd2(__hadd2(*(__half2*)&a.y, *(__half2*)&b.y), bb[1]);
                __half2 s2 = __hadd2(__hadd2(*(__half2*)&a.z, *(__half2*)&b.z), bb[2]);
                __half2 s3 = __hadd2(__hadd2(*(__half2*)&a.w, *(__half2*)&b.w), bb[3]);
                hw[q * 4 + 0] = *(uint32_t*)&s0;
                hw[q * 4 + 1] = *(uint32_t*)&s1;
                hw[q * 4 + 2] = *(uint32_t*)&s2;
                hw[q * 4 + 3] = *(uint32_t*)&s3;
            }
            // re-pair into permuted layout: local word u = 2g' + m',
            //   lo = local ch 16m' + g', hi = lo + 8
            const __half* hh = (const __half*)hw;
            uint32_t pw[16];
            #pragma unroll
            for (int u = 0; u < 16; u++) {
                int loc = ((u & 1) << 4) + (u >> 1);
                __half2 pr = __halves2half2(hh[loc], hh[loc + 8]);
                pw[u] = *(uint32_t*)&pr;
            }
            uint4* hdst = (uint4*)(HSRw + el2 * HSTRW + p4r * 16);
            hdst[0] = make_uint4(pw[0],  pw[1],  pw[2],  pw[3]);
            hdst[1] = make_uint4(pw[4],  pw[5],  pw[6],  pw[7]);
            hdst[2] = make_uint4(pw[8],  pw[9],  pw[10], pw[11]);
            hdst[3] = make_uint4(pw[12], pw[13], pw[14], pw[15]);
        }
        BARG();   // S1

        // ====== GEMM1': acc init = HSR(+b1) via LDS.64; += e @ W1e ===========
        float acc1[2][4][4];
        {
            const int woff = 16 * (w & 3) + 2 * g;   // permuted word pair base
            #pragma unroll
            for (int nt = 0; nt < 4; nt++) {
                int eA = e0w1 + 8 * nt + 2 * tig;
                uint2 u0 = *(const uint2*)(HSRw + eA * HSTRW + woff);
                uint2 u1 = *(const uint2*)(HSRw + (eA + 1) * HSTRW + woff);
                float2 a0 = __half22float2(*(__half2*)&u0.x);   // mt=0: (c, c+8)
                float2 a1 = __half22float2(*(__half2*)&u0.y);   // mt=1
                float2 b0 = __half22float2(*(__half2*)&u1.x);
                float2 b1f = __half22float2(*(__half2*)&u1.y);
                acc1[0][nt][0] = a0.x; acc1[0][nt][2] = a0.y;
                acc1[1][nt][0] = a1.x; acc1[1][nt][2] = a1.y;
                acc1[0][nt][1] = b0.x; acc1[0][nt][3] = b0.y;
                acc1[1][nt][1] = b1f.x; acc1[1][nt][3] = b1f.y;
            }
        }
        #pragma unroll
        for (int kt = 0; kt < 4; kt++) {
            uint32_t av[2][4], bv[2][4];
            ldsm4(av[0], aW1b + kt * 32);
            ldsm4(av[1], aW1b + 2304 + kt * 32);
            ldsm4(bv[0], bX1b + kt * 32);
            ldsm4(bv[1], bX1b + 6400 + kt * 32);
            #pragma unroll
            for (int mt = 0; mt < 2; mt++)
                #pragma unroll
                for (int np = 0; np < 2; np++) {
                    mma16(acc1[mt][2 * np],     av[mt], bv[np]);
                    mma16(acc1[mt][2 * np + 1], av[mt], bv[np] + 2);
                }
        }
        BARG();   // S2

        // ===== epilogue1: hid = relu(acc) -> X words 32+perm (STS.64) ========
        {
            const int woff = 32 + 16 * (w & 3) + 2 * g;
            #pragma unroll
            for (int nt = 0; nt < 4; nt++) {
                int eA = e0w1 + 8 * nt + 2 * tig;
                uint2 s0, s1;
                s0.x = packh2(fmaxf(acc1[0][nt][0], 0.f), fmaxf(acc1[0][nt][2], 0.f));
                s0.y = packh2(fmaxf(acc1[1][nt][0], 0.f), fmaxf(acc1[1][nt][2], 0.f));
                s1.x = packh2(fmaxf(acc1[0][nt][1], 0.f), fmaxf(acc1[0][nt][3], 0.f));
                s1.y = packh2(fmaxf(acc1[1][nt][1], 0.f), fmaxf(acc1[1][nt][3], 0.f));
                *(uint2*)(Xw + eA * XSTRW + woff)       = s0;
                *(uint2*)(Xw + (eA + 1) * XSTRW + woff) = s1;
            }
        }
        BARG();   // S3

        float acc2[2][4][4];
        #pragma unroll
        for (int mt = 0; mt < 2; mt++)
            #pragma unroll
            for (int nt = 0; nt < 4; nt++)
                #pragma unroll
                for (int q = 0; q < 4; q++) acc2[mt][nt][q] = 0.f;

        if (w < 4) {
            // ===== GEMM2: m = hid @ W2 (permuted K) -> mf -> scatter =========
            #pragma unroll
            for (int kt = 0; kt < 8; kt++) {
                uint32_t av[2][4], bv[2][4];
                ldsm4(av[0], aW2b + kt * 32);
                ldsm4(av[1], aW2b + 4352 + kt * 32);
                ldsm4(bv[0], bX2b + 128 + kt * 32);
                ldsm4(bv[1], bX2b + 6400 + 128 + kt * 32);
                #pragma unroll
                for (int mt = 0; mt < 2; mt++)
                    #pragma unroll
                    for (int np = 0; np < 2; np++) {
                        mma16(acc2[mt][2 * np],     av[mt], bv[np]);
                        mma16(acc2[mt][2 * np + 1], av[mt], bv[np] + 2);
                    }
            }
            #pragma unroll
            for (int mt = 0; mt < 2; mt++)
                #pragma unroll
                for (int nt = 0; nt < 4; nt++) {
                    int cA = c0w2 + 16 * mt + g;
                    int eA = e0w2 + 8 * nt + 2 * tig;
                    mf[eA * HSTRW + cA]           = acc2[mt][nt][0] + bi2[cA];
                    mf[(eA + 1) * HSTRW + cA]     = acc2[mt][nt][1] + bi2[cA];
                    mf[eA * HSTRW + cA + 8]       = acc2[mt][nt][2] + bi2[cA + 8];
                    mf[(eA + 1) * HSTRW + cA + 8] = acc2[mt][nt][3] + bi2[cA + 8];
                }
            asm volatile("bar.sync %0, 128;" :: "r"(barid2) : "memory");
            const int el = lt & 63;
            const int hf = (lt >> 6) & 1;
            const int r  = ridx[el];
            const float4* mrow4 = (const float4*)(mf + el * HSTRW + hf * 32);
            float* dstp = g_agg + (size_t)r * D + hf * 32;
            #pragma unroll
            for (int c4 = 0; c4 < 8; c4++)
                red4(dstp + c4 * 4, mrow4[c4]);
        } else {
            // ===== GEMM3: e @ We_e (K=64) + hid @ P (permuted K=128) =========
            #pragma unroll
            for (int kt = 0; kt < 4; kt++) {
                uint32_t av[2][4], bv[2][4];
                ldsm4(av[0], aWEeb + kt * 32);
                ldsm4(av[1], aWEeb + 2304 + kt * 32);
                ldsm4(bv[0], bX2b + kt * 32);
                ldsm4(bv[1], bX2b + 6400 + kt * 32);
                #pragma unroll
                for (int mt = 0; mt < 2; mt++)
                    #pragma unroll
                    for (int np = 0; np < 2; np++) {
                        mma16(acc2[mt][2 * np],     av[mt], bv[np]);
                        mma16(acc2[mt][2 * np + 1], av[mt], bv[np] + 2);
                    }
            }
            #pragma unroll
            for (int kt = 0; kt < 8; kt++) {
                uint32_t av[2][4], bv[2][4];
                ldsm4(av[0], aPb + kt * 32);
                ldsm4(av[1], aPb + 4352 + kt * 32);
                ldsm4(bv[0], bX2b + 128 + kt * 32);
                ldsm4(bv[1], bX2b + 6400 + 128 + kt * 32);
                #pragma unroll
                for (int mt = 0; mt < 2; mt++)
                    #pragma unroll
                    for (int np = 0; np < 2; np++) {
                        mma16(acc2[mt][2 * np],     av[mt], bv[np]);
                        mma16(acc2[mt][2 * np + 1], av[mt], bv[np] + 2);
                    }
            }
            #pragma unroll
            for (int mt = 0; mt < 2; mt++)
                #pragma unroll
                for (int nt = 0; nt < 4; nt++) {
                    int cA = c0w2 + 16 * mt + g;
                    int eA = e0w2 + 8 * nt + 2 * tig;
                    eout[eA * HSTRW + cA]           = fmaxf(acc2[mt][nt][0] + bie2[cA], 0.f);
                    eout[(eA + 1) * HSTRW + cA]     = fmaxf(acc2[mt][nt][1] + bie2[cA], 0.f);
                    eout[eA * HSTRW + cA + 8]       = fmaxf(acc2[mt][nt][2] + bie2[cA + 8], 0.f);
                    eout[(eA + 1) * HSTRW + cA + 8] = fmaxf(acc2[mt][nt][3] + bie2[cA + 8], 0.f);
                }
            asm volatile("bar.sync %0, 128;" :: "r"(barid3) : "memory");
            const int lt2 = lt - 128;
            float4* dst4 = (float4*)(out_e + (size_t)base * D);
            #pragma unroll
            for (int jj = 0; jj < 8; jj++) {
                int idx = lt2 + jj * 128;
                int row = idx >> 4, ch = idx & 15;
                dst4[idx] = *(const float4*)(eout + row * HSTRW + ch * 4);
            }
        }
    }
    #undef BARG
}

// ---------------- node kernel (fp16 mma): h_new = relu([h|agg] @ Wn + bn) ----
__global__ void __launch_bounds__(128)
node_kernel(const float* __restrict__ h,
            const float* __restrict__ Wn, const float* __restrict__ bn,
            float* __restrict__ out_h)
{
    extern __shared__ char smc[];
    uint32_t* WNw = (uint32_t*)(smc + NOFF_WN);
    float*    bnf = (float*)(smc + NOFF_BN);
    uint32_t* PW  = (uint32_t*)(smc + NOFF_PL);

    const int tid  = threadIdx.x;
    const int w    = tid >> 5;
    const int lane = tid & 31;
    const int g    = lane >> 2;
    const int tig  = lane & 3;
    const int swz  = tig << 3;

    // stage Wn [128][64] fragment order (natural K), rows padded to 68 words
    for (int i = tid; i < D * (DH / 2); i += 128) {
        int c = i >> 6, k2 = i & 63;
        WNw[c * 68 + k2] = packh2(Wn[(2 * k2) * D + c], Wn[(2 * k2 + 1) * D + c]);
    }
    if (tid < D) bnf[tid] = bn[tid];
    __syncthreads();

    const int base = blockIdx.x * 64;

    // gather: 2 threads per node (src 0 = h, src 1 = agg); K = 128 -> p 0..63
    {
        const int nl  = tid & 63;
        const int src = tid >> 6;
        const int node = base + nl;
        const float4* sp = (const float4*)((src ? g_agg : h) + (size_t)node * D);
        #pragma unroll
        for (int q = 0; q < 16; q++) {
            float4 v = (node < N_NODES) ? sp[q] : make_float4(0.f, 0.f, 0.f, 0.f);
            int p = src * 32 + q * 2;
            PW[p * 64 + (nl ^ ((p & 3) << 3))]             = packh2(v.x, v.y);
            PW[(p + 1) * 64 + (nl ^ (((p + 1) & 3) << 3))] = packh2(v.z, v.w);
        }
    }
    __syncthreads();

    const int c0 = 32 * (w & 1);
    const int n0 = 32 * (w >> 1);

    float acc[2][4][4];
    #pragma unroll
    for (int mt = 0; mt < 2; mt++)
        #pragma unroll
        for (int nt = 0; nt < 4; nt++)
            #pragma unroll
            for (int q = 0; q < 4; q++) acc[mt][nt][q] = 0.f;

    #pragma unroll
    for (int kt = 0; kt < 8; kt++) {
        const int k8 = kt * 8;
        uint32_t av[2][4];
        #pragma unroll
        for (int mt = 0; mt < 2; mt++) {
            int r = c0 + 16 * mt + g;
            av[mt][0] = WNw[r * 68 + k8 + tig];
            av[mt][1] = WNw[(r + 8) * 68 + k8 + tig];
            av[mt][2] = WNw[r * 68 + k8 + tig + 4];
            av[mt][3] = WNw[(r + 8) * 68 + k8 + tig + 4];
        }
        uint32_t bv[4][2];
        const int p0 = k8 + tig;
        #pragma unroll
        for (int nt = 0; nt < 4; nt++) {
            int es = (n0 + nt * 8 + g) ^ swz;
            bv[nt][0] = PW[p0 * 64 + es];
            bv[nt][1] = PW[(p0 + 4) * 64 + es];
        }
        #pragma unroll
        for (int mt = 0; mt < 2; mt++)
            #pragma unroll
            for (int nt = 0; nt < 4; nt++)
                mma16(acc[mt][nt], av[mt], bv[nt]);
    }

    #pragma unroll
    for (int mt = 0; mt < 2; mt++)
        #pragma unroll
        for (int nt = 0; nt < 4; nt++) {
            int cA = c0 + 16 * mt + g;
            int nA = n0 + 8 * nt + 2 * tig;
            int d0 = base + nA, d1 = base + nA + 1;
            if (d0 < N_NODES) {
                out_h[(size_t)d0 * D + cA]     = fmaxf(acc[mt][nt][0] + bnf[cA], 0.f);
                out_h[(size_t)d0 * D + cA + 8] = fmaxf(acc[mt][nt][2] + bnf[cA + 8], 0.f);
            }
            if (d1 < N_NODES) {
                out_h[(size_t)d1 * D + cA]     = fmaxf(acc[mt][nt][1] + bnf[cA], 0.f);
                out_h[(size_t)d1 * D + cA + 8] = fmaxf(acc[mt][nt][3] + bnf[cA + 8], 0.f);
            }
        }
}

// ---------------- launch -----------------------------------------------------
extern "C" void kernel_launch(void* const* d_in, const int* in_sizes, int n_in,
                              void* d_out, int out_size)
{
    const float* h        = (const float*)d_in[0];
    const float* e        = (const float*)d_in[1];
    const int*   senders  = (const int*)d_in[2];
    const int*   receivers= (const int*)d_in[3];
    const float* W1       = (const float*)d_in[4];
    const float* b1       = (const float*)d_in[5];
    const float* W2       = (const float*)d_in[6];
    const float* b2       = (const float*)d_in[7];
    const float* Wn       = (const float*)d_in[8];
    const float* bn       = (const float*)d_in[9];
    const float* We       = (const float*)d_in[10];
    const float* be       = (const float*)d_in[11];

    float* out_h = (float*)d_out;
    float* out_e = out_h + (size_t)N_NODES * D;

    cudaFuncSetAttribute(edge_kernel, cudaFuncAttributeMaxDynamicSharedMemorySize,
                         SMEM_EDGE_BYTES);
    cudaFuncSetAttribute(node_kernel, cudaFuncAttributeMaxDynamicSharedMemorySize,
                         SMEM_NODE_BYTES);

    zero_agg_kernel<<<(N_NODES * D / 4 + 255) / 256, 256>>>();
    pw_kernel<<<(DH * D + 255) / 256, 256>>>(W2, We, b2, be);
    pre_kernel<<<(N_NODES + 63) / 64, 256, SMEM_PRE_BYTES>>>(h, W1);
    edge_kernel<<<EK_GRID, EK_THREADS, SMEM_EDGE_BYTES>>>(
        h, e, senders, receivers, W1, b1, W2, b2, We, be, out_e);
    node_kernel<<<(N_NODES + 63) / 64, 128, SMEM_NODE_BYTES>>>(h, Wn, bn, out_h);
}

// round 17
// speedup vs baseline: 1.1073x; 1.0653x over previous
#include <cuda_runtime.h>
#include <cuda_fp16.h>
#include <cstdint>

#define N_NODES 100000
#define N_EDGES 1600000
#define D       64
#define DH      128
#define KIN     192

#define TILE_E   64
#define N_TILES  (N_EDGES / TILE_E)   // 25000
#define EK_GRID  148
#define EK_THREADS 512                // 2 groups x 256

// ---------------- edge-kernel smem byte offsets ------------------------------
#define OFF_W1E   0          // W1e^T fp16 [128 rows][36 w] = 18432
#define OFF_W2    18432      // W2^T [64 rows][68 w] = 17408 (permuted K)
#define OFF_WEE   35840      // We_e^T (K=64) [64 rows][36 w] = 9216
#define OFF_P     45056      // P^T [64 rows][68 w] = 17408 (permuted K)
#define OFF_BI1H  62464      // b1 half2 = 256
#define OFF_BI2   62720      // b2 fp32 = 256
#define OFF_BIE2  62976      // be' fp32 = 256
#define OFF_GRP   63232
// group block: X 64x100 w 25600 | HSR/mf 64x68 w 17408 | ridx 256
#define GRP_BYTES 43264
#define GOFF_HSR  25600
#define GOFF_RIDX 43008
#define SMEM_EDGE_BYTES (OFF_GRP + 2 * GRP_BYTES)   // 149760

#define XSTRW 100            // X row stride in words
#define HSTRW 68             // HSR/mf row stride in words

// ---------------- precompute-kernel smem -------------------------------------
#define POFF_WS   0
#define POFF_WR   18432
#define POFF_PL   36864
#define SMEM_PRE_BYTES 45056

// ---------------- node-kernel smem -------------------------------------------
#define NOFF_WN 0            // Wn fragment [64][68] w = 17408
#define NOFF_BN 17408        // 64 floats = 256
#define NOFF_PL 17664        // planes 64 p x 64 w = 16384
#define SMEM_NODE_BYTES 34048

// ---------------- helpers ----------------------------------------------------
__device__ __forceinline__ uint32_t packh2(float lo, float hi) {
    uint32_t d;
    asm("cvt.rn.f16x2.f32 %0, %1, %2;" : "=r"(d) : "f"(hi), "f"(lo));
    return d;
}
__device__ __forceinline__ void mma16(float* c, const uint32_t* a, const uint32_t* b) {
    asm volatile(
        "mma.sync.aligned.m16n8k16.row.col.f32.f16.f16.f32 "
        "{%0,%1,%2,%3}, {%4,%5,%6,%7}, {%8,%9}, {%0,%1,%2,%3};"
        : "+f"(c[0]), "+f"(c[1]), "+f"(c[2]), "+f"(c[3])
        : "r"(a[0]), "r"(a[1]), "r"(a[2]), "r"(a[3]), "r"(b[0]), "r"(b[1]));
}
__device__ __forceinline__ void ldsm4(uint32_t* r, uint32_t saddr) {
    asm volatile("ldmatrix.sync.aligned.m8n8.x4.shared.b16 {%0,%1,%2,%3}, [%4];"
        : "=r"(r[0]), "=r"(r[1]), "=r"(r[2]), "=r"(r[3]) : "r"(saddr));
}
__device__ __forceinline__ void red4(float* p, float4 v) {
    asm volatile("red.global.add.v4.f32 [%0], {%1,%2,%3,%4};"
        :: "l"(p), "f"(v.x), "f"(v.y), "f"(v.z), "f"(v.w) : "memory");
}
// dst[0..3] = a + b + c  (half2 lanes)
__device__ __forceinline__ void add3h2(__half2* dst, uint4 a, uint4 b, uint4 c) {
    dst[0] = __hadd2(__hadd2(*(__half2*)&a.x, *(__half2*)&b.x), *(__half2*)&c.x);
    dst[1] = __hadd2(__hadd2(*(__half2*)&a.y, *(__half2*)&b.y), *(__half2*)&c.y);
    dst[2] = __hadd2(__hadd2(*(__half2*)&a.z, *(__half2*)&b.z), *(__half2*)&c.z);
    dst[3] = __hadd2(__hadd2(*(__half2*)&a.w, *(__half2*)&b.w), *(__half2*)&c.w);
}

// ---------------- scratch ----------------------------------------------------
__device__ float  g_agg[(size_t)N_NODES * D];
__device__ __half g_H1[(size_t)N_NODES * DH];
__device__ __half g_H2[(size_t)N_NODES * DH];
__device__ __half g_P[DH * D];      // W2 @ We_m  (fp16)
__device__ float  g_be2[D];         // b2 @ We_m + be

__global__ void zero_agg_kernel() {
    size_t i = (size_t)blockIdx.x * blockDim.x + threadIdx.x;
    size_t n4 = (size_t)N_NODES * D / 4;
    if (i < n4) ((float4*)g_agg)[i] = make_float4(0.f, 0.f, 0.f, 0.f);
}

// ---------------- tiny: P = W2 @ We_m,  be' = b2 @ We_m + be -----------------
__global__ void __launch_bounds__(256)
pw_kernel(const float* __restrict__ W2, const float* __restrict__ We,
          const float* __restrict__ b2, const float* __restrict__ be)
{
    int i = blockIdx.x * 256 + threadIdx.x;
    if (i < DH * D) {
        int k = i / D, c = i % D;
        float s = 0.f;
        #pragma unroll 8
        for (int l = 0; l < D; l++)
            s += W2[k * D + l] * We[(D + l) * D + c];
        g_P[k * D + c] = __float2half_rn(s);
    }
    if (i < D) {
        float s = be[i];
        #pragma unroll 8
        for (int l = 0; l < D; l++)
            s += b2[l] * We[(D + l) * D + i];
        g_be2[i] = s;
    }
}

// ---------------- precompute: H1 = h@W1s, H2 = h@W1r -------------------------
__global__ void __launch_bounds__(256)
pre_kernel(const float* __restrict__ h, const float* __restrict__ W1)
{
    extern __shared__ char smc[];
    uint32_t* WSw = (uint32_t*)(smc + POFF_WS);
    uint32_t* WRw = (uint32_t*)(smc + POFF_WR);
    uint32_t* PW  = (uint32_t*)(smc + POFF_PL);

    const int tid  = threadIdx.x;
    const int w    = tid >> 5;
    const int lane = tid & 31;
    const int g    = lane >> 2;
    const int tig  = lane & 3;
    const int swz  = tig << 3;

    for (int i = tid; i < DH * 32; i += 256) {
        int c = i >> 5, k2 = i & 31;
        WSw[c * 36 + k2] = packh2(W1[(64 + 2 * k2) * DH + c],
                                  W1[(64 + 2 * k2 + 1) * DH + c]);
        WRw[c * 36 + k2] = packh2(W1[(128 + 2 * k2) * DH + c],
                                  W1[(128 + 2 * k2 + 1) * DH + c]);
    }
    __syncthreads();

    const int base = blockIdx.x * 64;
    {
        const int nl = tid & 63;
        const int p4 = tid >> 6;
        const int node = base + nl;
        #pragma unroll
        for (int q = 0; q < 4; q++) {
            float4 v = (node < N_NODES)
                ? ((const float4*)(h + (size_t)node * D))[p4 * 4 + q]
                : make_float4(0.f, 0.f, 0.f, 0.f);
            int p = p4 * 8 + q * 2;
            PW[p * 64 + (nl ^ ((p & 3) << 3))]             = packh2(v.x, v.y);
            PW[(p + 1) * 64 + (nl ^ (((p + 1) & 3) << 3))] = packh2(v.z, v.w);
        }
    }
    __syncthreads();

    const int c0 = (w & 3) * 32;
    const int n0 = (w >> 2) * 32;

    float accS[2][4][4], accR[2][4][4];
    #pragma unroll
    for (int mt = 0; mt < 2; mt++)
        #pragma unroll
        for (int nt = 0; nt < 4; nt++)
            #pragma unroll
            for (int q = 0; q < 4; q++) { accS[mt][nt][q] = 0.f; accR[mt][nt][q] = 0.f; }

    #pragma unroll
    for (int kt = 0; kt < 4; kt++) {
        const int k8 = kt * 8;
        uint32_t as[2][4], ar[2][4];
        #pragma unroll
        for (int mt = 0; mt < 2; mt++) {
            int r = c0 + 16 * mt + g;
            as[mt][0] = WSw[r * 36 + k8 + tig];
            as[mt][1] = WSw[(r + 8) * 36 + k8 + tig];
            as[mt][2] = WSw[r * 36 + k8 + tig + 4];
            as[mt][3] = WSw[(r + 8) * 36 + k8 + tig + 4];
            ar[mt][0] = WRw[r * 36 + k8 + tig];
            ar[mt][1] = WRw[(r + 8) * 36 + k8 + tig];
            ar[mt][2] = WRw[r * 36 + k8 + tig + 4];
            ar[mt][3] = WRw[(r + 8) * 36 + k8 + tig + 4];
        }
        uint32_t bv[4][2];
        const int p0 = k8 + tig;
        #pragma unroll
        for (int nt = 0; nt < 4; nt++) {
            int es = (n0 + nt * 8 + g) ^ swz;
            bv[nt][0] = PW[p0 * 64 + es];
            bv[nt][1] = PW[(p0 + 4) * 64 + es];
        }
        #pragma unroll
        for (int mt = 0; mt < 2; mt++)
            #pragma unroll
            for (int nt = 0; nt < 4; nt++) {
                mma16(accS[mt][nt], as[mt], bv[nt]);
                mma16(accR[mt][nt], ar[mt], bv[nt]);
            }
    }

    #pragma unroll
    for (int mt = 0; mt < 2; mt++)
        #pragma unroll
        for (int nt = 0; nt < 4; nt++) {
            int cA = c0 + 16 * mt + g;
            int nA = n0 + 8 * nt + 2 * tig;
            int d0 = base + nA, d1 = base + nA + 1;
            if (d0 < N_NODES) {
                g_H1[(size_t)d0 * DH + cA]     = __float2half_rn(accS[mt][nt][0]);
                g_H1[(size_t)d0 * DH + cA + 8] = __float2half_rn(accS[mt][nt][2]);
                g_H2[(size_t)d0 * DH + cA]     = __float2half_rn(accR[mt][nt][0]);
                g_H2[(size_t)d0 * DH + cA + 8] = __float2half_rn(accR[mt][nt][2]);
            }
            if (d1 < N_NODES) {
                g_H1[(size_t)d1 * DH + cA]     = __float2half_rn(accS[mt][nt][1]);
                g_H1[(size_t)d1 * DH + cA + 8] = __float2half_rn(accS[mt][nt][3]);
                g_H2[(size_t)d1 * DH + cA]     = __float2half_rn(accR[mt][nt][1]);
                g_H2[(size_t)d1 * DH + cA + 8] = __float2half_rn(accR[mt][nt][3]);
            }
        }
}

// ---------------- fused edge kernel ------------------------------------------
// hid K-permutation: K-slot word u ∈ [0,64) holds channels
//   lo = 32*(u>>4) + 16*(u&1) + ((u>>1)&7),  hi = lo + 8
__global__ void __launch_bounds__(EK_THREADS, 1)
edge_kernel(const float* __restrict__ h, const float* __restrict__ e,
            const int* __restrict__ senders, const int* __restrict__ receivers,
            const float* __restrict__ W1, const float* __restrict__ b1,
            const float* __restrict__ W2, const float* __restrict__ b2,
            const float* __restrict__ We, const float* __restrict__ be,
            float* __restrict__ out_e)
{
    extern __shared__ char smc[];
    uint32_t* W1w  = (uint32_t*)(smc + OFF_W1E);
    uint32_t* W2w  = (uint32_t*)(smc + OFF_W2);
    uint32_t* WEew = (uint32_t*)(smc + OFF_WEE);
    uint32_t* Pw   = (uint32_t*)(smc + OFF_P);
    uint32_t* b1h  = (uint32_t*)(smc + OFF_BI1H);
    float* bi2  = (float*)(smc + OFF_BI2);
    float* bie2 = (float*)(smc + OFF_BIE2);

    const int tid = threadIdx.x;

    // ---- stage weights + biases ---------------------------------------------
    for (int i = tid; i < DH * 32; i += EK_THREADS) {         // W1e (natural K)
        int c = i >> 5, k2 = i & 31;
        W1w[c * 36 + k2] = packh2(W1[(2 * k2) * DH + c], W1[(2 * k2 + 1) * DH + c]);
    }
    for (int i = tid; i < D * (DH / 2); i += EK_THREADS) {    // W2 (permuted K)
        int c = i >> 6, kp = i & 63;
        int lo = 32 * (kp >> 4) + 16 * (kp & 1) + ((kp >> 1) & 7);
        W2w[c * 68 + kp] = packh2(W2[lo * D + c], W2[(lo + 8) * D + c]);
    }
    for (int i = tid; i < D * 32; i += EK_THREADS) {          // We_e (natural K)
        int c = i >> 5, k2 = i & 31;
        WEew[c * 36 + k2] = packh2(We[(2 * k2) * D + c], We[(2 * k2 + 1) * D + c]);
    }
    for (int i = tid; i < D * (DH / 2); i += EK_THREADS) {    // P (permuted K)
        int c = i >> 6, kp = i & 63;
        int lo = 32 * (kp >> 4) + 16 * (kp & 1) + ((kp >> 1) & 7);
        __half2 h2 = __halves2half2(g_P[lo * D + c], g_P[(lo + 8) * D + c]);
        Pw[c * 68 + kp] = *(uint32_t*)&h2;
    }
    if (tid < D) b1h[tid]  = packh2(b1[2 * tid], b1[2 * tid + 1]);
    if (tid < D) bi2[tid]  = b2[tid];
    if (tid < D) bie2[tid] = g_be2[tid];
    __syncthreads();

    // ---- group-local state ---------------------------------------------------
    const int gi   = tid >> 8;
    const int lt   = tid & 255;
    const int w    = lt >> 5;
    const int lane = lt & 31;
    const int g    = lane >> 2;
    const int tig  = lane & 3;

    char* gbase = smc + OFF_GRP + gi * GRP_BYTES;
    uint32_t* Xw   = (uint32_t*)gbase;
    uint32_t* HSRw = (uint32_t*)(gbase + GOFF_HSR);
    float*    mf   = (float*)(gbase + GOFF_HSR);   // overlays HSR (time-disjoint)
    int*      ridx = (int*)(gbase + GOFF_RIDX);

    const uint32_t Xs   = (uint32_t)__cvta_generic_to_shared(Xw);
    const uint32_t W1s  = (uint32_t)__cvta_generic_to_shared(W1w);
    const uint32_t W2s  = (uint32_t)__cvta_generic_to_shared(W2w);
    const uint32_t WEes = (uint32_t)__cvta_generic_to_shared(WEew);
    const uint32_t Ps   = (uint32_t)__cvta_generic_to_shared(Pw);

    const int c0w1 = (w & 3) * 32;
    const int e0w1 = (w >> 2) * 32;
    const int wl   = w & 3;
    const int c0w2 = (wl & 1) * 32;
    const int e0w2 = (wl >> 1) * 32;
    const int barid  = gi + 1;       // group-wide (256)
    const int barid2 = gi + 3;       // w0-3 half-group (128)

    // ldmatrix lane-address components
    const int rA  = (lane & 7) + ((lane >> 3) & 1) * 8;
    const int cA4 = (lane >> 4) << 2;
    const int rB  = (lane & 7) + ((lane >> 4) << 3);
    const int cB4 = ((lane >> 3) & 1) << 2;

    const uint32_t aW1b  = W1s  + ((c0w1 + rA) * 36 + cA4) * 4;
    const uint32_t aW2b  = W2s  + ((c0w2 + rA) * 68 + cA4) * 4;
    const uint32_t aWEeb = WEes + ((c0w2 + rA) * 36 + cA4) * 4;
    const uint32_t aPb   = Ps   + ((c0w2 + rA) * 68 + cA4) * 4;
    const uint32_t bX1b  = Xs + ((e0w1 + rB) * XSTRW + cB4) * 4;
    const uint32_t bX2b  = Xs + ((e0w2 + rB) * XSTRW + cB4) * 4;

    // H-gather lane map: 8 lanes per row, 32B contiguous per lane
    const int slot = lt >> 3;        // 0..31
    const int j8   = lt & 7;
    const int ubase = 16 * (j8 >> 1) + (j8 & 1);   // permuted word base

    #define BARG() asm volatile("bar.sync %0, 256;" :: "r"(barid) : "memory")

    for (int tile = blockIdx.x * 2 + gi; tile < N_TILES; tile += 2 * gridDim.x) {
        const int base = tile * TILE_E;
        BARG();   // S0

        // ====== gather: e -> X rows; H1[s]+H2[r]+b1 -> HSR (permuted) ========
        {
            // --- e: fully coalesced linear loads, scatter-store to X rows ----
            const float4* e4 = (const float4*)(e + (size_t)base * D);
            #pragma unroll
            for (int q = 0; q < 4; q++) {
                int gidx = lt + q * 256;
                float4 v = e4[gidx];
                int ed = gidx >> 4, ch = gidx & 15;
                *(uint2*)(Xw + ed * XSTRW + ch * 2) =
                    make_uint2(packh2(v.x, v.y), packh2(v.z, v.w));
            }

            // --- H: thread handles edges slot & slot+32, ch 16*j8..16*j8+15 --
            const int eg0 = slot, eg1 = slot + 32;
            const int s0 = senders[base + eg0], r0 = receivers[base + eg0];
            const int s1 = senders[base + eg1], r1 = receivers[base + eg1];
            if (j8 == 0) { ridx[eg0] = r0; ridx[eg1] = r1; }

            const uint4* pa0 = (const uint4*)(g_H1 + (size_t)s0 * DH) + 2 * j8;
            const uint4* pa1 = (const uint4*)(g_H1 + (size_t)s1 * DH) + 2 * j8;
            const uint4* pb0 = (const uint4*)(g_H2 + (size_t)r0 * DH) + 2 * j8;
            const uint4* pb1 = (const uint4*)(g_H2 + (size_t)r1 * DH) + 2 * j8;
            uint4 A0a = pa0[0], A0b = pa0[1];
            uint4 B0a = pb0[0], B0b = pb0[1];
            uint4 A1a = pa1[0], A1b = pa1[1];
            uint4 B1a = pb1[0], B1b = pb1[1];
            const uint4* bb4 = (const uint4*)(b1h + 8 * j8);
            uint4 bw0 = bb4[0], bw1 = bb4[1];

            __half2 S0[8], S1[8];
            add3h2(S0,     A0a, B0a, bw0);
            add3h2(S0 + 4, A0b, B0b, bw1);
            add3h2(S1,     A1a, B1a, bw0);
            add3h2(S1 + 4, A1b, B1b, bw1);

            const __half* hsA = (const __half*)S0;
            const __half* hsB = (const __half*)S1;
            uint32_t* d0 = HSRw + eg0 * HSTRW + ubase;
            uint32_t* d1 = HSRw + eg1 * HSTRW + ubase;
            #pragma unroll
            for (int t = 0; t < 8; t++) {
                __half2 p0 = __halves2half2(hsA[t], hsA[t + 8]);
                __half2 p1 = __halves2half2(hsB[t], hsB[t + 8]);
                d0[2 * t] = *(uint32_t*)&p0;
                d1[2 * t] = *(uint32_t*)&p1;
            }
        }
        BARG();   // S1

        // ====== GEMM1': acc init = HSR(+b1) via LDS.64; += e @ W1e ===========
        float acc1[2][4][4];
        {
            const int woff = 16 * (w & 3) + 2 * g;
            #pragma unroll
            for (int nt = 0; nt < 4; nt++) {
                int eA = e0w1 + 8 * nt + 2 * tig;
                uint2 u0 = *(const uint2*)(HSRw + eA * HSTRW + woff);
                uint2 u1 = *(const uint2*)(HSRw + (eA + 1) * HSTRW + woff);
                float2 a0 = __half22float2(*(__half2*)&u0.x);
                float2 a1 = __half22float2(*(__half2*)&u0.y);
                float2 b0 = __half22float2(*(__half2*)&u1.x);
                float2 b1f = __half22float2(*(__half2*)&u1.y);
                acc1[0][nt][0] = a0.x; acc1[0][nt][2] = a0.y;
                acc1[1][nt][0] = a1.x; acc1[1][nt][2] = a1.y;
                acc1[0][nt][1] = b0.x; acc1[0][nt][3] = b0.y;
                acc1[1][nt][1] = b1f.x; acc1[1][nt][3] = b1f.y;
            }
        }
        #pragma unroll
        for (int kt = 0; kt < 4; kt++) {
            uint32_t av[2][4], bv[2][4];
            ldsm4(av[0], aW1b + kt * 32);
            ldsm4(av[1], aW1b + 2304 + kt * 32);
            ldsm4(bv[0], bX1b + kt * 32);
            ldsm4(bv[1], bX1b + 6400 + kt * 32);
            #pragma unroll
            for (int mt = 0; mt < 2; mt++)
                #pragma unroll
                for (int np = 0; np < 2; np++) {
                    mma16(acc1[mt][2 * np],     av[mt], bv[np]);
                    mma16(acc1[mt][2 * np + 1], av[mt], bv[np] + 2);
                }
        }
        BARG();   // S2

        // ===== epilogue1: hid = relu(acc) -> X words 32+perm (STS.64) ========
        {
            const int woff = 32 + 16 * (w & 3) + 2 * g;
            #pragma unroll
            for (int nt = 0; nt < 4; nt++) {
                int eA = e0w1 + 8 * nt + 2 * tig;
                uint2 s0, s1;
                s0.x = packh2(fmaxf(acc1[0][nt][0], 0.f), fmaxf(acc1[0][nt][2], 0.f));
                s0.y = packh2(fmaxf(acc1[1][nt][0], 0.f), fmaxf(acc1[1][nt][2], 0.f));
                s1.x = packh2(fmaxf(acc1[0][nt][1], 0.f), fmaxf(acc1[0][nt][3], 0.f));
                s1.y = packh2(fmaxf(acc1[1][nt][1], 0.f), fmaxf(acc1[1][nt][3], 0.f));
                *(uint2*)(Xw + eA * XSTRW + woff)       = s0;
                *(uint2*)(Xw + (eA + 1) * XSTRW + woff) = s1;
            }
        }
        BARG();   // S3

        float acc2[2][4][4];
        #pragma unroll
        for (int mt = 0; mt < 2; mt++)
            #pragma unroll
            for (int nt = 0; nt < 4; nt++)
                #pragma unroll
                for (int q = 0; q < 4; q++) acc2[mt][nt][q] = 0.f;

        if (w < 4) {
            // ===== GEMM2: m = hid @ W2 (permuted K) -> mf -> scatter =========
            #pragma unroll
            for (int kt = 0; kt < 8; kt++) {
                uint32_t av[2][4], bv[2][4];
                ldsm4(av[0], aW2b + kt * 32);
                ldsm4(av[1], aW2b + 4352 + kt * 32);
                ldsm4(bv[0], bX2b + 128 + kt * 32);
                ldsm4(bv[1], bX2b + 6400 + 128 + kt * 32);
                #pragma unroll
                for (int mt = 0; mt < 2; mt++)
                    #pragma unroll
                    for (int np = 0; np < 2; np++) {
                        mma16(acc2[mt][2 * np],     av[mt], bv[np]);
                        mma16(acc2[mt][2 * np + 1], av[mt], bv[np] + 2);
                    }
            }
            #pragma unroll
            for (int mt = 0; mt < 2; mt++)
                #pragma unroll
                for (int nt = 0; nt < 4; nt++) {
                    int cA = c0w2 + 16 * mt + g;
                    int eA = e0w2 + 8 * nt + 2 * tig;
                    mf[eA * HSTRW + cA]           = acc2[mt][nt][0] + bi2[cA];
                    mf[(eA + 1) * HSTRW + cA]     = acc2[mt][nt][1] + bi2[cA];
                    mf[eA * HSTRW + cA + 8]       = acc2[mt][nt][2] + bi2[cA + 8];
                    mf[(eA + 1) * HSTRW + cA + 8] = acc2[mt][nt][3] + bi2[cA + 8];
                }
            asm volatile("bar.sync %0, 128;" :: "r"(barid2) : "memory");
            const int el = lt & 63;
            const int hf = (lt >> 6) & 1;
            const int r  = ridx[el];
            const float4* mrow4 = (const float4*)(mf + el * HSTRW + hf * 32);
            float* dstp = g_agg + (size_t)r * D + hf * 32;
            #pragma unroll
            for (int c4 = 0; c4 < 8; c4++)
                red4(dstp + c4 * 4, mrow4[c4]);
        } else {
            // ===== GEMM3: e @ We_e (K=64) + hid @ P (permuted K=128) =========
            #pragma unroll
            for (int kt = 0; kt < 4; kt++) {
                uint32_t av[2][4], bv[2][4];
                ldsm4(av[0], aWEeb + kt * 32);
                ldsm4(av[1], aWEeb + 2304 + kt * 32);
                ldsm4(bv[0], bX2b + kt * 32);
                ldsm4(bv[1], bX2b + 6400 + kt * 32);
                #pragma unroll
                for (int mt = 0; mt < 2; mt++)
                    #pragma unroll
                    for (int np = 0; np < 2; np++) {
                        mma16(acc2[mt][2 * np],     av[mt], bv[np]);
                        mma16(acc2[mt][2 * np + 1], av[mt], bv[np] + 2);
                    }
            }
            #pragma unroll
            for (int kt = 0; kt < 8; kt++) {
                uint32_t av[2][4], bv[2][4];
                ldsm4(av[0], aPb + kt * 32);
                ldsm4(av[1], aPb + 4352 + kt * 32);
                ldsm4(bv[0], bX2b + 128 + kt * 32);
                ldsm4(bv[1], bX2b + 6400 + 128 + kt * 32);
                #pragma unroll
                for (int mt = 0; mt < 2; mt++)
                    #pragma unroll
                    for (int np = 0; np < 2; np++) {
                        mma16(acc2[mt][2 * np],     av[mt], bv[np]);
                        mma16(acc2[mt][2 * np + 1], av[mt], bv[np] + 2);
                    }
            }
            // ===== epilogue3: e_new = relu(acc + be') -> gmem (direct) =======
            #pragma unroll
            for (int mt = 0; mt < 2; mt++)
                #pragma unroll
                for (int nt = 0; nt < 4; nt++) {
                    int cA = c0w2 + 16 * mt + g;
                    int eA = e0w2 + 8 * nt + 2 * tig;
                    float* d0 = out_e + (size_t)(base + eA) * D;
                    float* d1 = out_e + (size_t)(base + eA + 1) * D;
                    d0[cA]     = fmaxf(acc2[mt][nt][0] + bie2[cA], 0.f);
                    d1[cA]     = fmaxf(acc2[mt][nt][1] + bie2[cA], 0.f);
                    d0[cA + 8] = fmaxf(acc2[mt][nt][2] + bie2[cA + 8], 0.f);
                    d1[cA + 8] = fmaxf(acc2[mt][nt][3] + bie2[cA + 8], 0.f);
                }
        }
    }
    #undef BARG
}

// ---------------- node kernel (fp16 mma): h_new = relu([h|agg] @ Wn + bn) ----
__global__ void __launch_bounds__(128)
node_kernel(const float* __restrict__ h,
            const float* __restrict__ Wn, const float* __restrict__ bn,
            float* __restrict__ out_h)
{
    extern __shared__ char smc[];
    uint32_t* WNw = (uint32_t*)(smc + NOFF_WN);
    float*    bnf = (float*)(smc + NOFF_BN);
    uint32_t* PW  = (uint32_t*)(smc + NOFF_PL);

    const int tid  = threadIdx.x;
    const int w    = tid >> 5;
    const int lane = tid & 31;
    const int g    = lane >> 2;
    const int tig  = lane & 3;
    const int swz  = tig << 3;

    for (int i = tid; i < D * (DH / 2); i += 128) {
        int c = i >> 6, k2 = i & 63;
        WNw[c * 68 + k2] = packh2(Wn[(2 * k2) * D + c], Wn[(2 * k2 + 1) * D + c]);
    }
    if (tid < D) bnf[tid] = bn[tid];
    __syncthreads();

    const int base = blockIdx.x * 64;

    {
        const int nl  = tid & 63;
        const int src = tid >> 6;
        const int node = base + nl;
        const float4* sp = (const float4*)((src ? g_agg : h) + (size_t)node * D);
        #pragma unroll
        for (int q = 0; q < 16; q++) {
            float4 v = (node < N_NODES) ? sp[q] : make_float4(0.f, 0.f, 0.f, 0.f);
            int p = src * 32 + q * 2;
            PW[p * 64 + (nl ^ ((p & 3) << 3))]             = packh2(v.x, v.y);
            PW[(p + 1) * 64 + (nl ^ (((p + 1) & 3) << 3))] = packh2(v.z, v.w);
        }
    }
    __syncthreads();

    const int c0 = 32 * (w & 1);
    const int n0 = 32 * (w >> 1);

    float acc[2][4][4];
    #pragma unroll
    for (int mt = 0; mt < 2; mt++)
        #pragma unroll
        for (int nt = 0; nt < 4; nt++)
            #pragma unroll
            for (int q = 0; q < 4; q++) acc[mt][nt][q] = 0.f;

    #pragma unroll
    for (int kt = 0; kt < 8; kt++) {
        const int k8 = kt * 8;
        uint32_t av[2][4];
        #pragma unroll
        for (int mt = 0; mt < 2; mt++) {
            int r = c0 + 16 * mt + g;
            av[mt][0] = WNw[r * 68 + k8 + tig];
            av[mt][1] = WNw[(r + 8) * 68 + k8 + tig];
            av[mt][2] = WNw[r * 68 + k8 + tig + 4];
            av[mt][3] = WNw[(r + 8) * 68 + k8 + tig + 4];
        }
        uint32_t bv[4][2];
        const int p0 = k8 + tig;
        #pragma unroll
        for (int nt = 0; nt < 4; nt++) {
            int es = (n0 + nt * 8 + g) ^ swz;
            bv[nt][0] = PW[p0 * 64 + es];
            bv[nt][1] = PW[(p0 + 4) * 64 + es];
        }
        #pragma unroll
        for (int mt = 0; mt < 2; mt++)
            #pragma unroll
            for (int nt = 0; nt < 4; nt++)
                mma16(acc[mt][nt], av[mt], bv[nt]);
    }

    #pragma unroll
    for (int mt = 0; mt < 2; mt++)
        #pragma unroll
        for (int nt = 0; nt < 4; nt++) {
            int cA = c0 + 16 * mt + g;
            int nA = n0 + 8 * nt + 2 * tig;
            int d0 = base + nA, d1 = base + nA + 1;
            if (d0 < N_NODES) {
                out_h[(size_t)d0 * D + cA]     = fmaxf(acc[mt][nt][0] + bnf[cA], 0.f);
                out_h[(size_t)d0 * D + cA + 8] = fmaxf(acc[mt][nt][2] + bnf[cA + 8], 0.f);
            }
            if (d1 < N_NODES) {
                out_h[(size_t)d1 * D + cA]     = fmaxf(acc[mt][nt][1] + bnf[cA], 0.f);
                out_h[(size_t)d1 * D + cA + 8] = fmaxf(acc[mt][nt][3] + bnf[cA + 8], 0.f);
            }
        }
}

// ---------------- launch -----------------------------------------------------
extern "C" void kernel_launch(void* const* d_in, const int* in_sizes, int n_in,
                              void* d_out, int out_size)
{
    const float* h        = (const float*)d_in[0];
    const float* e        = (const float*)d_in[1];
    const int*   senders  = (const int*)d_in[2];
    const int*   receivers= (const int*)d_in[3];
    const float* W1       = (const float*)d_in[4];
    const float* b1       = (const float*)d_in[5];
    const float* W2       = (const float*)d_in[6];
    const float* b2       = (const float*)d_in[7];
    const float* Wn       = (const float*)d_in[8];
    const float* bn       = (const float*)d_in[9];
    const float* We       = (const float*)d_in[10];
    const float* be       = (const float*)d_in[11];

    float* out_h = (float*)d_out;
    float* out_e = out_h + (size_t)N_NODES * D;

    cudaFuncSetAttribute(edge_kernel, cudaFuncAttributeMaxDynamicSharedMemorySize,
                         SMEM_EDGE_BYTES);
    cudaFuncSetAttribute(node_kernel, cudaFuncAttributeMaxDynamicSharedMemorySize,
                         SMEM_NODE_BYTES);

    zero_agg_kernel<<<(N_NODES * D / 4 + 255) / 256, 256>>>();
    pw_kernel<<<(DH * D + 255) / 256, 256>>>(W2, We, b2, be);
    pre_kernel<<<(N_NODES + 63) / 64, 256, SMEM_PRE_BYTES>>>(h, W1);
    edge_kernel<<<EK_GRID, EK_THREADS, SMEM_EDGE_BYTES>>>(
        h, e, senders, receivers, W1, b1, W2, b2, We, be, out_e);
    node_kernel<<<(N_NODES + 63) / 64, 128, SMEM_NODE_BYTES>>>(h, Wn, bn, out_h);
}